// round 17
// baseline (speedup 1.0000x reference)
#include <cuda_runtime.h>

#define BATCH 262144
#define DIM   128
#define K     10

#define T1        128
#define TILE_ROWS 256                    // 2 rows per thread
#define NTILES    (BATCH / TILE_ROWS)    // 1024
#define NBLK1     512                    // 2 tiles per block; all resident
#define NCHUNK    8                      // 16 dims per chunk
#define NSTAGE    3                      // ring depth
#define CH_F4     4                      // float4 per row per chunk
#define BUF_F4    (TILE_ROWS * CH_F4)    // 1024 float4 = 16 KB per slot
#define RPB       (2 * TILE_ROWS)        // 512 rows per block

// Scratch (no allocs). g_part fully overwritten per launch; counters return to 0.
__device__ float g_part[NBLK1][K];
__device__ int   g_ctr  = 0;
__device__ int   g_done = 0;

typedef unsigned long long u64;

__device__ __forceinline__ void unpack2(u64 v, float& lo, float& hi) {
    asm("mov.b64 {%0, %1}, %2;" : "=f"(lo), "=f"(hi) : "l"(v));
}
__device__ __forceinline__ void fma2(u64& acc, u64 a, u64 b) {
    asm("fma.rn.f32x2 %0, %1, %2, %0;" : "+l"(acc) : "l"(a), "l"(b));
}
__device__ __forceinline__ void cp_async16(unsigned smem_addr, const void* g) {
    asm volatile("cp.async.cg.shared.global [%0], [%1], 16;"
                 :: "r"(smem_addr), "l"(g) : "memory");
}
__device__ __forceinline__ void cp_commit() {
    asm volatile("cp.async.commit_group;" ::: "memory");
}
__device__ __forceinline__ void cp_wait2() {
    asm volatile("cp.async.wait_group 2;" ::: "memory");
}
__device__ __forceinline__ void cp_wait1() {
    asm volatile("cp.async.wait_group 1;" ::: "memory");
}
__device__ __forceinline__ void cp_wait0() {
    asm volatile("cp.async.wait_group 0;" ::: "memory");
}

// Fused kernel: phase 1 = q + colsum partials (R16 warp-private ring, 2 tiles);
// software grid barrier; phase 2 = finalize colsums + p for own 512 rows.
// __launch_bounds__(128,4): 4 blocks/SM guaranteed -> all 512 blocks resident.
__global__ void __launch_bounds__(T1, 4) k_fused(
    const float* __restrict__ z,
    const float* __restrict__ c,
    float* __restrict__ qout,
    float* __restrict__ pout)
{
    __shared__ float4 s_buf[NSTAGE][BUF_F4];   // 3 x 16 KB (reused in phase 2)
    __shared__ float4 s_c[K][DIM / 4];         // 5120 B
    __shared__ float  s_cn[K];
    __shared__ float  s_part[4][K];
    __shared__ float  s_invf[K];

    const int tid  = threadIdx.x;
    const int lane = tid & 31;
    const int wrp  = tid >> 5;
    const int skey = (tid >> 1) & 3;           // swizzle key; same for tid+128
    const unsigned sb = (unsigned)__cvta_generic_to_shared(&s_buf[0][0]);

    for (int i = tid; i < K * DIM / 4; i += T1)
        ((float4*)s_c)[i] = ((const float4*)c)[i];
    __syncthreads();
    if (tid < K) {
        float s = 0.0f;
        #pragma unroll
        for (int d = 0; d < DIM / 4; d++) {
            float4 v = s_c[tid][d];
            s = fmaf(v.x, v.x, fmaf(v.y, v.y, fmaf(v.z, v.z, fmaf(v.w, v.w, s))));
        }
        s_cn[tid] = s;
    }
    __syncthreads();

    const ulonglong2* sc2 = reinterpret_cast<const ulonglong2*>(s_c);

    float csum[K];
    #pragma unroll
    for (int j = 0; j < K; j++) csum[j] = 0.0f;

    // ---------------- Phase 1: two tiles ----------------
    #pragma unroll 1
    for (int tt = 0; tt < 2; tt++) {
        const int t = blockIdx.x * 2 + tt;

        // Warp-private stage of chunk k: rows {w*32..+31} U {+128}, 64B each.
        auto stage = [&](int slot, int k) {
            const float4* zt = (const float4*)z + (size_t)t * TILE_ROWS * 32 + k * CH_F4;
            const unsigned base = sb + (unsigned)slot * (BUF_F4 * 16);
            #pragma unroll
            for (int k2 = 0; k2 < 8; k2++) {
                const int g  = k2 * 32 + lane;     // [0, 256) within warp
                const int rl = g >> 2;             // local row 0..63
                const int i  = g & 3;
                const int row = wrp * 32 + ((rl < 32) ? rl : (96 + rl));
                cp_async16(base + (unsigned)(row * CH_F4 + (i ^ ((row >> 1) & 3))) * 16,
                           zt + (size_t)row * 32 + i);
            }
            cp_commit();
        };

        stage(0, 0);
        stage(1, 1);

        u64 dot0[K], dot1[K], zn0 = 0ull, zn1 = 0ull;
        #pragma unroll
        for (int j = 0; j < K; j++) { dot0[j] = 0ull; dot1[j] = 0ull; }

        #pragma unroll
        for (int k = 0; k < NCHUNK; k++) {
            if (k + 2 < NCHUNK) stage((k + 2) % NSTAGE, k + 2);
            if (k + 2 < NCHUNK)      cp_wait2();
            else if (k + 1 < NCHUNK) cp_wait1();
            else                     cp_wait0();

            const ulonglong2* b2 =
                reinterpret_cast<const ulonglong2*>(&s_buf[k % NSTAGE][0]);
            #pragma unroll
            for (int i = 0; i < CH_F4; i++) {
                const int isw = i ^ skey;
                ulonglong2 a0 = b2[tid * CH_F4 + isw];
                ulonglong2 a1 = b2[(tid + 128) * CH_F4 + isw];
                fma2(zn0, a0.x, a0.x); fma2(zn0, a0.y, a0.y);
                fma2(zn1, a1.x, a1.x); fma2(zn1, a1.y, a1.y);
                #pragma unroll
                for (int j = 0; j < K; j++) {
                    ulonglong2 cc = sc2[j * (DIM / 4) + k * CH_F4 + i];
                    fma2(dot0[j], a0.x, cc.x); fma2(dot0[j], a0.y, cc.y);
                    fma2(dot1[j], a1.x, cc.x); fma2(dot1[j], a1.y, cc.y);
                }
            }
        }

        float lo, hi;
        #pragma unroll
        for (int rr = 0; rr < 2; rr++) {
            unpack2(rr ? zn1 : zn0, lo, hi);
            const float zz1 = 1.0f + (lo + hi);
            float q[K], rsum = 0.0f;
            #pragma unroll
            for (int j = 0; j < K; j++) {
                unpack2(rr ? dot1[j] : dot0[j], lo, hi);
                const float d = lo + hi;
                const float v = __fdividef(1.0f, fmaf(-2.0f, d, zz1 + s_cn[j]));
                q[j] = v; rsum += v;
            }
            const float inv = __fdividef(1.0f, rsum);
            const int row = t * TILE_ROWS + rr * 128 + tid;
            float* orow = qout + (size_t)row * K;
            #pragma unroll
            for (int j = 0; j < K; j++) { q[j] *= inv; csum[j] += q[j]; }
            #pragma unroll
            for (int m = 0; m < 5; m++) {
                float2 v; v.x = q[2 * m]; v.y = q[2 * m + 1];
                *(float2*)(orow + 2 * m) = v;
            }
        }
        __syncthreads();   // all reads of s_buf done before next tile restages
    }

    // Block colsum partial -> g_part[blockIdx.x]
    #pragma unroll
    for (int j = 0; j < K; j++) {
        float v = csum[j];
        #pragma unroll
        for (int m = 16; m > 0; m >>= 1) v += __shfl_xor_sync(0xFFFFFFFFu, v, m);
        if (lane == 0) s_part[wrp][j] = v;
    }
    __syncthreads();
    if (tid < K)
        g_part[blockIdx.x][tid] =
            s_part[0][tid] + s_part[1][tid] + s_part[2][tid] + s_part[3][tid];

    // ---------------- Grid barrier (all 512 blocks resident) ----------------
    __threadfence();
    __syncthreads();
    if (tid == 0) {
        atomicAdd(&g_ctr, 1);
        while (*((volatile int*)&g_ctr) < NBLK1) __nanosleep(128);
    }
    __syncthreads();
    __threadfence();

    // ---------------- Finalize colsums (redundant per block, L2-fed) --------
    {
        float acc[K];
        #pragma unroll
        for (int j = 0; j < K; j++)
            acc[j] = g_part[tid][j] + g_part[tid + 128][j]
                   + g_part[tid + 256][j] + g_part[tid + 384][j];
        #pragma unroll
        for (int j = 0; j < K; j++) {
            float v = acc[j];
            #pragma unroll
            for (int m = 16; m > 0; m >>= 1) v += __shfl_xor_sync(0xFFFFFFFFu, v, m);
            if (lane == 0) s_part[wrp][j] = v;
        }
        __syncthreads();
        if (tid < K)
            s_invf[tid] = __fdividef(1.0f,
                s_part[0][tid] + s_part[1][tid] + s_part[2][tid] + s_part[3][tid]);
        __syncthreads();
    }

    // ---------------- Phase 2: p for own 512 rows (q hot in L1/L2) ----------
    {
        float* s_q = (float*)&s_buf[0][0];            // 20480 B
        float* s_p = (float*)&s_buf[0][0] + RPB * K;  // next 20480 B

        const float4* qg = (const float4*)(qout + (size_t)blockIdx.x * RPB * K);
        #pragma unroll
        for (int i = 0; i < RPB * K / 4 / T1; i++)    // 10 per thread
            ((float4*)s_q)[i * T1 + tid] = qg[i * T1 + tid];
        __syncthreads();

        #pragma unroll
        for (int m = 0; m < RPB / T1; m++) {          // 4 rows per thread
            const float* qr = s_q + (m * T1 + tid) * K;
            float*       pr = s_p + (m * T1 + tid) * K;
            float w[K], s = 0.0f;
            #pragma unroll
            for (int j = 0; j < K; j++) {
                float v = qr[j];
                w[j] = v * v * s_invf[j];
                s += w[j];
            }
            const float inv = __fdividef(1.0f, s);
            #pragma unroll
            for (int j = 0; j < K; j++) pr[j] = w[j] * inv;
        }
        __syncthreads();

        float4* pg = (float4*)(pout + (size_t)blockIdx.x * RPB * K);
        #pragma unroll
        for (int i = 0; i < RPB * K / 4 / T1; i++)
            pg[i * T1 + tid] = ((const float4*)s_p)[i * T1 + tid];
    }

    // ---------------- Counter reset (last block; deterministic) -------------
    __syncthreads();
    if (tid == 0) {
        if (atomicAdd(&g_done, 1) == NBLK1 - 1) {
            g_ctr  = 0;
            g_done = 0;
            __threadfence();
        }
    }
}

extern "C" void kernel_launch(void* const* d_in, const int* in_sizes, int n_in,
                              void* d_out, int out_size) {
    const float* z = (const float*)d_in[0];
    const float* c = (const float*)d_in[1];
    float* qout = (float*)d_out;
    float* pout = (float*)d_out + (size_t)BATCH * K;

    k_fused<<<NBLK1, T1>>>(z, c, qout, pout);
}